// round 1
// baseline (speedup 1.0000x reference)
#include <cuda_runtime.h>

#define BB 4
#define TT 2048
#define DD 1024
#define HH 16
#define DH 64
#define MROWS (BB*TT)          // 8192

// scratch (static device allocs are allowed; cudaMalloc is not)
__device__ float g_qkv[3][(size_t)BB*HH*TT*DH];   // q,k,v in [B,H,T,dh]
__device__ float g_att[(size_t)BB*TT*DD];         // attention output [B,T,D]

// ---------------------------------------------------------------------------
// Kernel 1: QKV projection GEMM.  out[m,n] = sum_k x[m,k] * W[n,k] + b[n]
// M=8192, N=1024, K=1024, z selects {Wq,Wk,Wv}. Output scattered to
// [B,H,T,dh] layout directly.
// ---------------------------------------------------------------------------
#define GBM 64
#define GBN 64
#define GBK 16
#define GPAD 68   // padded smem row (floats), keeps 16B alignment per row

__global__ __launch_bounds__(256) void qkv_gemm_kernel(
    const float* __restrict__ x,
    const float* __restrict__ Wq, const float* __restrict__ bq,
    const float* __restrict__ Wk, const float* __restrict__ bk,
    const float* __restrict__ Wv, const float* __restrict__ bv)
{
    __shared__ float As[GBK][GPAD];   // As[k][m]
    __shared__ float Bs[GBK][GPAD];   // Bs[k][n]

    const int which = blockIdx.z;
    const float* __restrict__ W    = (which == 0) ? Wq : (which == 1) ? Wk : Wv;
    const float* __restrict__ bias = (which == 0) ? bq : (which == 1) ? bk : bv;
    float* __restrict__ out = g_qkv[which];

    const int m0 = blockIdx.y * GBM;
    const int n0 = blockIdx.x * GBN;
    const int tid = threadIdx.x;
    const int tx = tid & 15;          // 0..15 -> n micro
    const int ty = tid >> 4;          // 0..15 -> m micro
    const int lr  = tid >> 2;         // 0..63 load row
    const int lc4 = tid & 3;          // 0..3  load col (float4)

    float acc[4][4] = {};

    for (int k0 = 0; k0 < DD; k0 += GBK) {
        float4 avec = *(const float4*)&x[(size_t)(m0 + lr) * DD + k0 + lc4 * 4];
        float4 bvec = *(const float4*)&W[(size_t)(n0 + lr) * DD + k0 + lc4 * 4];
        __syncthreads();
        As[lc4*4+0][lr] = avec.x; As[lc4*4+1][lr] = avec.y;
        As[lc4*4+2][lr] = avec.z; As[lc4*4+3][lr] = avec.w;
        Bs[lc4*4+0][lr] = bvec.x; Bs[lc4*4+1][lr] = bvec.y;
        Bs[lc4*4+2][lr] = bvec.z; Bs[lc4*4+3][lr] = bvec.w;
        __syncthreads();

        #pragma unroll
        for (int kk = 0; kk < GBK; kk++) {
            float4 a = *(const float4*)&As[kk][ty * 4];
            float4 b = *(const float4*)&Bs[kk][tx * 4];
            float am[4] = {a.x, a.y, a.z, a.w};
            float bn[4] = {b.x, b.y, b.z, b.w};
            #pragma unroll
            for (int i = 0; i < 4; i++)
                #pragma unroll
                for (int j = 0; j < 4; j++)
                    acc[i][j] = fmaf(am[i], bn[j], acc[i][j]);
        }
    }

    // epilogue: add bias, scatter to [B,H,T,dh]
    const int ncol = n0 + tx * 4;           // first of 4 contiguous cols
    const int h = ncol >> 6;
    const int d = ncol & 63;                // d..d+3 within one head
    float4 b4 = *(const float4*)&bias[ncol];
    #pragma unroll
    for (int i = 0; i < 4; i++) {
        int m = m0 + ty * 4 + i;
        int bb = m >> 11;
        int t  = m & (TT - 1);
        float4 r;
        r.x = acc[i][0] + b4.x; r.y = acc[i][1] + b4.y;
        r.z = acc[i][2] + b4.z; r.w = acc[i][3] + b4.w;
        *(float4*)&out[(((size_t)(bb * HH + h)) * TT + t) * DH + d] = r;
    }
}

// ---------------------------------------------------------------------------
// Kernel 2: causal flash attention, fp32.
// One thread per query row (128 rows/CTA), K/V tiles of 32 rows in smem.
// ---------------------------------------------------------------------------
#define AQ 128
#define AK 32

__global__ __launch_bounds__(128) void attn_kernel()
{
    __shared__ float Ks[AK][DH];
    __shared__ float Vs[AK][DH];

    const int tid = threadIdx.x;
    const int bh  = blockIdx.y;                 // 0..63
    const int q0  = blockIdx.x * AQ;
    const int t   = q0 + tid;                   // this thread's query row

    const float* __restrict__ Qg = g_qkv[0] + ((size_t)bh * TT + t) * DH;
    const float* __restrict__ Kg = g_qkv[1] + (size_t)bh * TT * DH;
    const float* __restrict__ Vg = g_qkv[2] + (size_t)bh * TT * DH;

    float4 q4[16];
    #pragma unroll
    for (int c = 0; c < 16; c++) q4[c] = ((const float4*)Qg)[c];

    float o[DH];
    #pragma unroll
    for (int d = 0; d < DH; d++) o[d] = 0.f;
    float mrun = -1e30f, lrun = 0.f;

    const int kend = q0 + AQ;                   // max k needed (exclusive)

    for (int j0 = 0; j0 < kend; j0 += AK) {
        __syncthreads();
        // cooperative tile load: 512 float4 each for K and V
        const float4* ksrc = (const float4*)(Kg + (size_t)j0 * DH);
        const float4* vsrc = (const float4*)(Vg + (size_t)j0 * DH);
        #pragma unroll
        for (int it = 0; it < (AK * DH / 4) / 128; it++) {
            int i = tid + it * 128;
            ((float4*)Ks)[i] = ksrc[i];
            ((float4*)Vs)[i] = vsrc[i];
        }
        __syncthreads();

        // pass 1: scores for this tile
        float s[AK];
        float tmax = -1e30f;
        #pragma unroll
        for (int j = 0; j < AK; j++) {
            const float4* kr = (const float4*)Ks[j];
            float a0 = 0.f, a1 = 0.f, a2 = 0.f, a3 = 0.f;
            #pragma unroll
            for (int c = 0; c < 16; c++) {
                float4 kv = kr[c];
                a0 = fmaf(q4[c].x, kv.x, a0);
                a1 = fmaf(q4[c].y, kv.y, a1);
                a2 = fmaf(q4[c].z, kv.z, a2);
                a3 = fmaf(q4[c].w, kv.w, a3);
            }
            float sc = ((a0 + a1) + (a2 + a3)) * 0.125f;   // 1/sqrt(64)
            if (j0 + j > t) sc = -1e30f;                    // causal mask
            s[j] = sc;
            tmax = fmaxf(tmax, sc);
        }

        // online softmax rescale
        float mnew = fmaxf(mrun, tmax);
        float corr = __expf(mrun - mnew);
        lrun *= corr;
        #pragma unroll
        for (int d = 0; d < DH; d++) o[d] *= corr;
        mrun = mnew;

        // pass 2: accumulate P*V
        #pragma unroll
        for (int j = 0; j < AK; j++) {
            float p = __expf(s[j] - mrun);
            lrun += p;
            const float4* vr = (const float4*)Vs[j];
            #pragma unroll
            for (int c = 0; c < 16; c++) {
                float4 vv = vr[c];
                o[c*4+0] = fmaf(p, vv.x, o[c*4+0]);
                o[c*4+1] = fmaf(p, vv.y, o[c*4+1]);
                o[c*4+2] = fmaf(p, vv.z, o[c*4+2]);
                o[c*4+3] = fmaf(p, vv.w, o[c*4+3]);
            }
        }
    }

    const float inv = 1.f / lrun;
    const int bb = bh >> 4;
    const int h  = bh & 15;
    float* __restrict__ dst = g_att + ((size_t)(bb * TT + t)) * DD + h * DH;
    #pragma unroll
    for (int c = 0; c < 16; c++) {
        float4 r;
        r.x = o[c*4+0] * inv; r.y = o[c*4+1] * inv;
        r.z = o[c*4+2] * inv; r.w = o[c*4+3] * inv;
        ((float4*)dst)[c] = r;
    }
}

// ---------------------------------------------------------------------------
// Kernel 3: residual add + LayerNorm.  One CTA per row, 256 threads.
// ---------------------------------------------------------------------------
__global__ __launch_bounds__(256) void ln_kernel(
    const float* __restrict__ x,
    const float* __restrict__ gamma,
    const float* __restrict__ beta,
    float* __restrict__ out)
{
    __shared__ float ybuf[DD];
    __shared__ float red1[8], red2[8];
    __shared__ float s_mean, s_rstd;

    const int row = blockIdx.x;
    const int tid = threadIdx.x;
    const size_t base = (size_t)row * DD;

    float4 av = ((const float4*)(g_att + base))[tid];
    float4 xv = ((const float4*)(x + base))[tid];
    float4 y;
    y.x = av.x + xv.x; y.y = av.y + xv.y;
    y.z = av.z + xv.z; y.w = av.w + xv.w;
    ((float4*)ybuf)[tid] = y;

    float s1 = y.x + y.y + y.z + y.w;
    float s2 = y.x*y.x + y.y*y.y + y.z*y.z + y.w*y.w;
    #pragma unroll
    for (int off = 16; off > 0; off >>= 1) {
        s1 += __shfl_xor_sync(0xffffffffu, s1, off);
        s2 += __shfl_xor_sync(0xffffffffu, s2, off);
    }
    if ((tid & 31) == 0) { red1[tid >> 5] = s1; red2[tid >> 5] = s2; }
    __syncthreads();
    if (tid < 32) {
        float r1 = (tid < 8) ? red1[tid] : 0.f;
        float r2 = (tid < 8) ? red2[tid] : 0.f;
        #pragma unroll
        for (int off = 4; off > 0; off >>= 1) {
            r1 += __shfl_xor_sync(0xffffffffu, r1, off);
            r2 += __shfl_xor_sync(0xffffffffu, r2, off);
        }
        if (tid == 0) {
            float mean = r1 * (1.f / DD);
            float var  = r2 * (1.f / DD) - mean * mean;
            s_mean = mean;
            s_rstd = rsqrtf(var + 1e-5f);
        }
    }
    __syncthreads();

    const float mean = s_mean, rstd = s_rstd;
    float4 yl = ((const float4*)ybuf)[tid];
    float4 g4 = ((const float4*)gamma)[tid];
    float4 b4 = ((const float4*)beta)[tid];
    float4 r;
    r.x = (yl.x - mean) * rstd * g4.x + b4.x;
    r.y = (yl.y - mean) * rstd * g4.y + b4.y;
    r.z = (yl.z - mean) * rstd * g4.z + b4.z;
    r.w = (yl.w - mean) * rstd * g4.w + b4.w;
    ((float4*)(out + base))[tid] = r;
}

// ---------------------------------------------------------------------------
extern "C" void kernel_launch(void* const* d_in, const int* in_sizes, int n_in,
                              void* d_out, int out_size)
{
    const float* x     = (const float*)d_in[0];
    const float* Wq    = (const float*)d_in[1];
    const float* bq    = (const float*)d_in[2];
    const float* Wk    = (const float*)d_in[3];
    const float* bk    = (const float*)d_in[4];
    const float* Wv    = (const float*)d_in[5];
    const float* bv    = (const float*)d_in[6];
    const float* gamma = (const float*)d_in[7];
    const float* beta  = (const float*)d_in[8];
    float* out = (float*)d_out;

    dim3 g1(DD / GBN, MROWS / GBM, 3);
    qkv_gemm_kernel<<<g1, 256>>>(x, Wq, bq, Wk, bk, Wv, bv);

    dim3 g2(TT / AQ, BB * HH);
    attn_kernel<<<g2, 128>>>();

    ln_kernel<<<MROWS, 256>>>(x, gamma, beta, out);
}

// round 2
// speedup vs baseline: 1.5641x; 1.5641x over previous
#include <cuda_runtime.h>

#define BB 4
#define TT 2048
#define DD 1024
#define HH 16
#define DH 64
#define MROWS (BB*TT)          // 8192

// scratch: Q,K stored d-major [bh][dh][T]; V natural [bh][T][dh]
__device__ float g_q[(size_t)BB*HH*DH*TT];
__device__ float g_k[(size_t)BB*HH*DH*TT];
__device__ float g_v[(size_t)BB*HH*TT*DH];
__device__ float g_att[(size_t)BB*TT*DD];         // attention output [B,T,D]

// ---------------------------------------------------------------------------
// Kernel 1: QKV projection GEMM.  out[m,n] = sum_k x[m,k] * W[n,k] + b[n]
// 128x128 tile, 8x8 microtile (2x 4-wide groups, 16B stride -> conflict-free),
// double-buffered smem with register prefetch.
// ---------------------------------------------------------------------------
#define GBM 128
#define GBN 128
#define GBK 16
#define GPAD 132

__global__ __launch_bounds__(256) void qkv_gemm_kernel(
    const float* __restrict__ x,
    const float* __restrict__ Wq, const float* __restrict__ bq,
    const float* __restrict__ Wk, const float* __restrict__ bk,
    const float* __restrict__ Wv, const float* __restrict__ bv)
{
    __shared__ float As[2][GBK][GPAD];   // As[buf][k][m]
    __shared__ float Bs[2][GBK][GPAD];   // Bs[buf][k][n]

    const int which = blockIdx.z;
    const float* __restrict__ W    = (which == 0) ? Wq : (which == 1) ? Wk : Wv;
    const float* __restrict__ bias = (which == 0) ? bq : (which == 1) ? bk : bv;

    const int m0 = blockIdx.y * GBM;
    const int n0 = blockIdx.x * GBN;
    const int tid = threadIdx.x;
    const int tx = tid & 15;          // n micro
    const int ty = tid >> 4;          // m micro
    const int lr = tid >> 1;          // 0..127 load row
    const int lk = (tid & 1) * 8;     // 0 or 8

    const float* __restrict__ xg = x + (size_t)(m0 + lr) * DD + lk;
    const float* __restrict__ wg = W + (size_t)(n0 + lr) * DD + lk;

    float acc[8][8] = {};

    // prologue: stage 0
    {
        float4 a0 = *(const float4*)(xg);
        float4 a1 = *(const float4*)(xg + 4);
        float4 b0 = *(const float4*)(wg);
        float4 b1 = *(const float4*)(wg + 4);
        As[0][lk+0][lr] = a0.x; As[0][lk+1][lr] = a0.y; As[0][lk+2][lr] = a0.z; As[0][lk+3][lr] = a0.w;
        As[0][lk+4][lr] = a1.x; As[0][lk+5][lr] = a1.y; As[0][lk+6][lr] = a1.z; As[0][lk+7][lr] = a1.w;
        Bs[0][lk+0][lr] = b0.x; Bs[0][lk+1][lr] = b0.y; Bs[0][lk+2][lr] = b0.z; Bs[0][lk+3][lr] = b0.w;
        Bs[0][lk+4][lr] = b1.x; Bs[0][lk+5][lr] = b1.y; Bs[0][lk+6][lr] = b1.z; Bs[0][lk+7][lr] = b1.w;
    }
    __syncthreads();

    int buf = 0;
    const int NSTAGE = DD / GBK;     // 64
    for (int s = 0; s < NSTAGE; s++) {
        float4 na0, na1, nb0, nb1;
        if (s < NSTAGE - 1) {
            const float* xp = xg + (size_t)(s + 1) * GBK;
            const float* wp = wg + (size_t)(s + 1) * GBK;
            na0 = *(const float4*)(xp);
            na1 = *(const float4*)(xp + 4);
            nb0 = *(const float4*)(wp);
            nb1 = *(const float4*)(wp + 4);
        }

        #pragma unroll
        for (int kk = 0; kk < GBK; kk++) {
            float4 a0 = *(const float4*)&As[buf][kk][ty * 4];
            float4 a1 = *(const float4*)&As[buf][kk][64 + ty * 4];
            float4 b0 = *(const float4*)&Bs[buf][kk][tx * 4];
            float4 b1 = *(const float4*)&Bs[buf][kk][64 + tx * 4];
            float am[8] = {a0.x, a0.y, a0.z, a0.w, a1.x, a1.y, a1.z, a1.w};
            float bn[8] = {b0.x, b0.y, b0.z, b0.w, b1.x, b1.y, b1.z, b1.w};
            #pragma unroll
            for (int i = 0; i < 8; i++)
                #pragma unroll
                for (int j = 0; j < 8; j++)
                    acc[i][j] = fmaf(am[i], bn[j], acc[i][j]);
        }

        if (s < NSTAGE - 1) {
            buf ^= 1;
            As[buf][lk+0][lr] = na0.x; As[buf][lk+1][lr] = na0.y; As[buf][lk+2][lr] = na0.z; As[buf][lk+3][lr] = na0.w;
            As[buf][lk+4][lr] = na1.x; As[buf][lk+5][lr] = na1.y; As[buf][lk+6][lr] = na1.z; As[buf][lk+7][lr] = na1.w;
            Bs[buf][lk+0][lr] = nb0.x; Bs[buf][lk+1][lr] = nb0.y; Bs[buf][lk+2][lr] = nb0.z; Bs[buf][lk+3][lr] = nb0.w;
            Bs[buf][lk+4][lr] = nb1.x; Bs[buf][lk+5][lr] = nb1.y; Bs[buf][lk+6][lr] = nb1.z; Bs[buf][lk+7][lr] = nb1.w;
            __syncthreads();
        }
    }

    // epilogue
    if (which == 2) {
        // V: natural [bh][t][dh]
        #pragma unroll
        for (int i = 0; i < 8; i++) {
            int m = m0 + (i >> 2) * 64 + ty * 4 + (i & 3);
            int bb = m >> 11;
            int t  = m & (TT - 1);
            #pragma unroll
            for (int jg = 0; jg < 2; jg++) {
                int cg = n0 + jg * 64 + tx * 4;     // global col of first elem
                int h = cg >> 6;
                int d = cg & 63;
                float4 r;
                r.x = acc[i][jg*4+0] + bias[cg+0];
                r.y = acc[i][jg*4+1] + bias[cg+1];
                r.z = acc[i][jg*4+2] + bias[cg+2];
                r.w = acc[i][jg*4+3] + bias[cg+3];
                *(float4*)&g_v[(((size_t)(bb * HH + h)) * TT + t) * DH + d] = r;
            }
        }
    } else {
        // Q or K: d-major [bh][dh][t]
        float* __restrict__ out = (which == 0) ? g_q : g_k;
        #pragma unroll
        for (int j = 0; j < 8; j++) {
            int col = n0 + (j >> 2) * 64 + tx * 4 + (j & 3);
            int h = col >> 6;
            int d = col & 63;
            float bj = bias[col];
            #pragma unroll
            for (int g = 0; g < 2; g++) {
                int m = m0 + g * 64 + ty * 4;
                int bb = m >> 11;
                int t  = m & (TT - 1);
                float4 r;
                r.x = acc[g*4+0][j] + bj;
                r.y = acc[g*4+1][j] + bj;
                r.z = acc[g*4+2][j] + bj;
                r.w = acc[g*4+3][j] + bj;
                *(float4*)&out[(((size_t)(bb * HH + h)) * DH + d) * TT + t] = r;
            }
        }
    }
}

// ---------------------------------------------------------------------------
// Kernel 2: causal flash attention, fp32, register-tiled (FA-2 style).
// CTA: 256 threads, 64x64 S tile, 4x4 microtiles for QK^T and P.V.
// Q,K read d-major (no transpose needed).
// ---------------------------------------------------------------------------
#define BQ 64
#define BK 64
#define APAD 68
#define ATTN_SMEM_BYTES (4 * 64 * APAD * 4)

__global__ __launch_bounds__(256) void attn_kernel()
{
    extern __shared__ float sm[];
    float* Qs = sm;                 // [d][r]   (Q pre-scaled by 1/8)
    float* Ks = sm + 64 * APAD;     // [d][c]
    float* Vs = sm + 2 * 64 * APAD; // [j][d]
    float* Ps = sm + 3 * 64 * APAD; // [j][r]

    const int tid = threadIdx.x;
    const int tx = tid & 15;
    const int ty = tid >> 4;
    const int bh = blockIdx.y;                    // 0..63
    const int qt = gridDim.x - 1 - blockIdx.x;    // heavy tiles first
    const int q0 = qt * BQ;

    const float* __restrict__ Qg = g_q + (size_t)bh * DH * TT;   // [d][t]
    const float* __restrict__ Kg = g_k + (size_t)bh * DH * TT;   // [d][t]
    const float* __restrict__ Vg = g_v + (size_t)bh * TT * DH;   // [t][d]

    // load Q tile (scaled): Qs[d][r] = Qg[d][q0+r] * 0.125
    #pragma unroll
    for (int it = 0; it < 4; it++) {
        int idx = tid + it * 256;       // 0..1023
        int d  = idx >> 4;
        int c4 = (idx & 15) * 4;
        float4 v = *(const float4*)&Qg[(size_t)d * TT + q0 + c4];
        float* dst = &Qs[d * APAD + c4];
        dst[0] = v.x * 0.125f; dst[1] = v.y * 0.125f;
        dst[2] = v.z * 0.125f; dst[3] = v.w * 0.125f;
    }

    float o[4][4] = {};
    float mrow[4] = {-1e30f, -1e30f, -1e30f, -1e30f};
    float lrow[4] = {};

    for (int j0 = 0; j0 <= q0; j0 += BK) {
        __syncthreads();
        #pragma unroll
        for (int it = 0; it < 4; it++) {
            int idx = tid + it * 256;
            int r  = idx >> 4;
            int c4 = (idx & 15) * 4;
            float4 kv = *(const float4*)&Kg[(size_t)r * TT + j0 + c4];
            *(float4*)&Ks[r * APAD + c4] = kv;
            float4 vv = *(const float4*)&Vg[(size_t)(j0 + r) * DH + c4];
            *(float4*)&Vs[r * APAD + c4] = vv;
        }
        __syncthreads();

        // S tile: s[i][j] = sum_d Qs[d][ty*4+i] * Ks[d][tx*4+j]
        float s[4][4] = {};
        #pragma unroll
        for (int k = 0; k < 64; k++) {
            float4 a = *(const float4*)&Qs[k * APAD + ty * 4];
            float4 b = *(const float4*)&Ks[k * APAD + tx * 4];
            float am[4] = {a.x, a.y, a.z, a.w};
            float bn[4] = {b.x, b.y, b.z, b.w};
            #pragma unroll
            for (int i = 0; i < 4; i++)
                #pragma unroll
                for (int j = 0; j < 4; j++)
                    s[i][j] = fmaf(am[i], bn[j], s[i][j]);
        }

        if (j0 == q0) {     // diagonal tile: causal mask
            #pragma unroll
            for (int i = 0; i < 4; i++)
                #pragma unroll
                for (int j = 0; j < 4; j++)
                    if (tx * 4 + j > ty * 4 + i) s[i][j] = -1e30f;
        }

        // online softmax per row
        #pragma unroll
        for (int i = 0; i < 4; i++) {
            float tm = fmaxf(fmaxf(s[i][0], s[i][1]), fmaxf(s[i][2], s[i][3]));
            tm = fmaxf(tm, __shfl_xor_sync(0xffffffffu, tm, 1));
            tm = fmaxf(tm, __shfl_xor_sync(0xffffffffu, tm, 2));
            tm = fmaxf(tm, __shfl_xor_sync(0xffffffffu, tm, 4));
            tm = fmaxf(tm, __shfl_xor_sync(0xffffffffu, tm, 8));
            float mnew = fmaxf(mrow[i], tm);
            float corr = __expf(mrow[i] - mnew);
            mrow[i] = mnew;
            float p0 = __expf(s[i][0] - mnew);
            float p1 = __expf(s[i][1] - mnew);
            float p2 = __expf(s[i][2] - mnew);
            float p3 = __expf(s[i][3] - mnew);
            s[i][0] = p0; s[i][1] = p1; s[i][2] = p2; s[i][3] = p3;
            lrow[i] = lrow[i] * corr + ((p0 + p1) + (p2 + p3));
            o[i][0] *= corr; o[i][1] *= corr; o[i][2] *= corr; o[i][3] *= corr;
        }

        // write P transposed: Ps[c][r]
        #pragma unroll
        for (int j = 0; j < 4; j++) {
            float4 pv = make_float4(s[0][j], s[1][j], s[2][j], s[3][j]);
            *(float4*)&Ps[(tx * 4 + j) * APAD + ty * 4] = pv;
        }
        __syncthreads();

        // O += P.V : o[i][j] += sum_k Ps[k][ty*4+i] * Vs[k][tx*4+j]
        #pragma unroll
        for (int k = 0; k < 64; k++) {
            float4 a = *(const float4*)&Ps[k * APAD + ty * 4];
            float4 b = *(const float4*)&Vs[k * APAD + tx * 4];
            float am[4] = {a.x, a.y, a.z, a.w};
            float bn[4] = {b.x, b.y, b.z, b.w};
            #pragma unroll
            for (int i = 0; i < 4; i++)
                #pragma unroll
                for (int j = 0; j < 4; j++)
                    o[i][j] = fmaf(am[i], bn[j], o[i][j]);
        }
    }

    // final: reduce l across tx, normalize, store
    const int bb = bh >> 4;
    const int h  = bh & 15;
    #pragma unroll
    for (int i = 0; i < 4; i++) {
        float l = lrow[i];
        l += __shfl_xor_sync(0xffffffffu, l, 1);
        l += __shfl_xor_sync(0xffffffffu, l, 2);
        l += __shfl_xor_sync(0xffffffffu, l, 4);
        l += __shfl_xor_sync(0xffffffffu, l, 8);
        float inv = 1.f / l;
        int t = q0 + ty * 4 + i;
        float4 r;
        r.x = o[i][0] * inv; r.y = o[i][1] * inv;
        r.z = o[i][2] * inv; r.w = o[i][3] * inv;
        *(float4*)&g_att[((size_t)(bb * TT + t)) * DD + h * DH + tx * 4] = r;
    }
}

// ---------------------------------------------------------------------------
// Kernel 3: residual add + LayerNorm.  One CTA per row, 256 threads.
// ---------------------------------------------------------------------------
__global__ __launch_bounds__(256) void ln_kernel(
    const float* __restrict__ x,
    const float* __restrict__ gamma,
    const float* __restrict__ beta,
    float* __restrict__ out)
{
    __shared__ float ybuf[DD];
    __shared__ float red1[8], red2[8];
    __shared__ float s_mean, s_rstd;

    const int row = blockIdx.x;
    const int tid = threadIdx.x;
    const size_t base = (size_t)row * DD;

    float4 av = ((const float4*)(g_att + base))[tid];
    float4 xv = ((const float4*)(x + base))[tid];
    float4 y;
    y.x = av.x + xv.x; y.y = av.y + xv.y;
    y.z = av.z + xv.z; y.w = av.w + xv.w;
    ((float4*)ybuf)[tid] = y;

    float s1 = y.x + y.y + y.z + y.w;
    float s2 = y.x*y.x + y.y*y.y + y.z*y.z + y.w*y.w;
    #pragma unroll
    for (int off = 16; off > 0; off >>= 1) {
        s1 += __shfl_xor_sync(0xffffffffu, s1, off);
        s2 += __shfl_xor_sync(0xffffffffu, s2, off);
    }
    if ((tid & 31) == 0) { red1[tid >> 5] = s1; red2[tid >> 5] = s2; }
    __syncthreads();
    if (tid < 32) {
        float r1 = (tid < 8) ? red1[tid] : 0.f;
        float r2 = (tid < 8) ? red2[tid] : 0.f;
        #pragma unroll
        for (int off = 4; off > 0; off >>= 1) {
            r1 += __shfl_xor_sync(0xffffffffu, r1, off);
            r2 += __shfl_xor_sync(0xffffffffu, r2, off);
        }
        if (tid == 0) {
            float mean = r1 * (1.f / DD);
            float var  = r2 * (1.f / DD) - mean * mean;
            s_mean = mean;
            s_rstd = rsqrtf(var + 1e-5f);
        }
    }
    __syncthreads();

    const float mean = s_mean, rstd = s_rstd;
    float4 yl = ((const float4*)ybuf)[tid];
    float4 g4 = ((const float4*)gamma)[tid];
    float4 b4 = ((const float4*)beta)[tid];
    float4 r;
    r.x = (yl.x - mean) * rstd * g4.x + b4.x;
    r.y = (yl.y - mean) * rstd * g4.y + b4.y;
    r.z = (yl.z - mean) * rstd * g4.z + b4.z;
    r.w = (yl.w - mean) * rstd * g4.w + b4.w;
    ((float4*)(out + base))[tid] = r;
}

// ---------------------------------------------------------------------------
extern "C" void kernel_launch(void* const* d_in, const int* in_sizes, int n_in,
                              void* d_out, int out_size)
{
    const float* x     = (const float*)d_in[0];
    const float* Wq    = (const float*)d_in[1];
    const float* bq    = (const float*)d_in[2];
    const float* Wk    = (const float*)d_in[3];
    const float* bk    = (const float*)d_in[4];
    const float* Wv    = (const float*)d_in[5];
    const float* bv    = (const float*)d_in[6];
    const float* gamma = (const float*)d_in[7];
    const float* beta  = (const float*)d_in[8];
    float* out = (float*)d_out;

    cudaFuncSetAttribute(attn_kernel,
                         cudaFuncAttributeMaxDynamicSharedMemorySize,
                         ATTN_SMEM_BYTES);

    dim3 g1(DD / GBN, MROWS / GBM, 3);
    qkv_gemm_kernel<<<g1, 256>>>(x, Wq, bq, Wk, bk, Wv, bv);

    dim3 g2(TT / BQ, BB * HH);
    attn_kernel<<<g2, 256, ATTN_SMEM_BYTES>>>();

    ln_kernel<<<MROWS, 256>>>(x, gamma, beta, out);
}

// round 4
// speedup vs baseline: 2.1737x; 1.3898x over previous
#include <cuda_runtime.h>
#include <cuda_bf16.h>
#include <cstdint>

#define BB 4
#define TT 2048
#define DD 1024
#define HH 16
#define DH 64
#define MROWS (BB*TT)          // 8192

// scratch: Q,K stored d-major [bh][dh][T]; V natural [bh][T][dh]
__device__ float g_q[(size_t)BB*HH*DH*TT];
__device__ float g_k[(size_t)BB*HH*DH*TT];
__device__ float g_v[(size_t)BB*HH*TT*DH];
__device__ float g_att[(size_t)BB*TT*DD];

// bf16 split operands
__device__ __nv_bfloat16 g_x_hi[(size_t)MROWS*DD];
__device__ __nv_bfloat16 g_x_lo[(size_t)MROWS*DD];
__device__ __nv_bfloat16 g_w_hi[3][(size_t)DD*DD];
__device__ __nv_bfloat16 g_w_lo[3][(size_t)DD*DD];

// ---------------------------------------------------------------------------
// helpers (baseline PTX only: cp.async + ldmatrix + mma.sync, sm_80+)
// ---------------------------------------------------------------------------
__device__ __forceinline__ uint32_t smem_u32(const void* p) {
    uint32_t a;
    asm("{ .reg .u64 t; cvta.to.shared.u64 t, %1; cvt.u32.u64 %0, t; }" : "=r"(a) : "l"(p));
    return a;
}
#define CP_ASYNC16(dst, src) \
    asm volatile("cp.async.cg.shared.global [%0], [%1], 16;" :: "r"(dst), "l"(src) : "memory")
#define CP_COMMIT() asm volatile("cp.async.commit_group;" ::: "memory")
#define CP_WAIT(n)  asm volatile("cp.async.wait_group %0;" :: "n"(n) : "memory")

#define LDMX4(r, addr) \
    asm volatile("ldmatrix.sync.aligned.m8n8.x4.shared.b16 {%0,%1,%2,%3}, [%4];" \
        : "=r"((r)[0]), "=r"((r)[1]), "=r"((r)[2]), "=r"((r)[3]) : "r"(addr))

#define MMA_BF16(c, a, b0, b1) \
    asm volatile("mma.sync.aligned.m16n8k16.row.col.f32.bf16.bf16.f32 " \
        "{%0,%1,%2,%3}, {%4,%5,%6,%7}, {%8,%9}, {%0,%1,%2,%3};" \
        : "+f"((c)[0]), "+f"((c)[1]), "+f"((c)[2]), "+f"((c)[3]) \
        : "r"((a)[0]), "r"((a)[1]), "r"((a)[2]), "r"((a)[3]), "r"(b0), "r"(b1))

// ---------------------------------------------------------------------------
// Kernel 0: fp32 -> (bf16 hi, bf16 lo) split
// ---------------------------------------------------------------------------
__global__ __launch_bounds__(256) void split_kernel(
    const float* __restrict__ src,
    __nv_bfloat16* __restrict__ hi,
    __nv_bfloat16* __restrict__ lo, int n4)
{
    int i = blockIdx.x * blockDim.x + threadIdx.x;
    if (i >= n4) return;
    float4 v = ((const float4*)src)[i];
    __nv_bfloat16 h0 = __float2bfloat16_rn(v.x);
    __nv_bfloat16 h1 = __float2bfloat16_rn(v.y);
    __nv_bfloat16 h2 = __float2bfloat16_rn(v.z);
    __nv_bfloat16 h3 = __float2bfloat16_rn(v.w);
    __nv_bfloat16 l0 = __float2bfloat16_rn(v.x - __bfloat162float(h0));
    __nv_bfloat16 l1 = __float2bfloat16_rn(v.y - __bfloat162float(h1));
    __nv_bfloat16 l2 = __float2bfloat16_rn(v.z - __bfloat162float(h2));
    __nv_bfloat16 l3 = __float2bfloat16_rn(v.w - __bfloat162float(h3));
    ((__nv_bfloat162*)hi)[2*i]   = __nv_bfloat162(h0, h1);
    ((__nv_bfloat162*)hi)[2*i+1] = __nv_bfloat162(h2, h3);
    ((__nv_bfloat162*)lo)[2*i]   = __nv_bfloat162(l0, l1);
    ((__nv_bfloat162*)lo)[2*i+1] = __nv_bfloat162(l2, l3);
}

// ---------------------------------------------------------------------------
// Kernel 1: QKV GEMM, mma.sync bf16-split, 128x128x32 tile, cp.async 2-stage.
// D = x @ W^T + b = Ah.Bh + Ah.Bl + Al.Bh   (fp32 accumulate)
// ---------------------------------------------------------------------------
#define RSTR 80                 // smem row stride bytes (32 bf16 data + pad)
#define OPB  (128 * RSTR)       // 10240 bytes per operand per buffer
#define BUFB (4 * OPB)          // 40960
#define GEMM_SMEM (2 * BUFB)    // 81920

__global__ __launch_bounds__(256) void qkv_mma_kernel(
    const float* __restrict__ bq,
    const float* __restrict__ bk,
    const float* __restrict__ bv)
{
    extern __shared__ uint8_t dsm[];
    const uint32_t sbase = smem_u32(dsm);

    const int which = blockIdx.z;
    const __nv_bfloat16* __restrict__ Ah = g_x_hi;
    const __nv_bfloat16* __restrict__ Al = g_x_lo;
    const __nv_bfloat16* __restrict__ Bh = g_w_hi[which];
    const __nv_bfloat16* __restrict__ Bl = g_w_lo[which];
    const float* __restrict__ bias = (which == 0) ? bq : (which == 1) ? bk : bv;

    const int m0 = blockIdx.y * 128;
    const int n0 = blockIdx.x * 128;
    const int tid = threadIdx.x;
    const int wid = tid >> 5;
    const int lid = tid & 31;
    const int warp_m = (wid & 1) * 64;      // 2 warps over M
    const int warp_n = (wid >> 1) * 32;     // 4 warps over N
    const int lrow = lid & 15;
    const int lhalf = lid >> 4;

    float acc[4][4][4] = {};

    // cp.async staging: idx 0..511 per operand; r=idx>>2 row, q=idx&3 (16B)
    auto load_chunk = [&](int c, int buf) {
        const uint32_t sb = sbase + buf * BUFB;
        #pragma unroll
        for (int i = 0; i < 2; i++) {
            int idx = tid + 256 * i;
            int r = idx >> 2, q = idx & 3;
            uint32_t so = r * RSTR + q * 16;
            size_t goA = (size_t)(m0 + r) * DD + c * 32 + q * 8;
            size_t goB = (size_t)(n0 + r) * DD + c * 32 + q * 8;
            CP_ASYNC16(sb + so,           Ah + goA);
            CP_ASYNC16(sb + OPB + so,     Al + goA);
            CP_ASYNC16(sb + 2*OPB + so,   Bh + goB);
            CP_ASYNC16(sb + 3*OPB + so,   Bl + goB);
        }
    };

    load_chunk(0, 0);
    CP_COMMIT();

    int buf = 0;
    #pragma unroll 1
    for (int c = 0; c < 32; c++) {
        if (c + 1 < 32) { load_chunk(c + 1, buf ^ 1); CP_COMMIT(); }
        if (c + 1 < 32) { CP_WAIT(1); } else { CP_WAIT(0); }
        __syncthreads();

        const uint32_t aw = sbase + buf * BUFB;
        #pragma unroll
        for (int ks = 0; ks < 2; ks++) {
            uint32_t ah[4][4], al[4][4], bh2[2][4], bl2[2][4];
            #pragma unroll
            for (int am = 0; am < 4; am++) {
                uint32_t addr = aw + (warp_m + am * 16 + lrow) * RSTR + ks * 32 + lhalf * 16;
                LDMX4(ah[am], addr);
                LDMX4(al[am], addr + OPB);
            }
            #pragma unroll
            for (int g = 0; g < 2; g++) {
                uint32_t addr = aw + 2*OPB + (warp_n + g * 16 + lrow) * RSTR + ks * 32 + lhalf * 16;
                LDMX4(bh2[g], addr);
                LDMX4(bl2[g], addr + OPB);
            }
            #pragma unroll
            for (int am = 0; am < 4; am++)
                #pragma unroll
                for (int an = 0; an < 4; an++) {
                    int g = an >> 1, s = an & 1;
                    MMA_BF16(acc[am][an], ah[am], bh2[g][s], bh2[g][s+2]);
                    MMA_BF16(acc[am][an], ah[am], bl2[g][s], bl2[g][s+2]);
                    MMA_BF16(acc[am][an], al[am], bh2[g][s], bh2[g][s+2]);
                }
        }
        __syncthreads();
        buf ^= 1;
    }

    // epilogue: C frag c0,c1 -> (row, col..col+1); c2,c3 -> (row+8, ...)
    #pragma unroll
    for (int am = 0; am < 4; am++) {
        #pragma unroll
        for (int an = 0; an < 4; an++) {
            int m = m0 + warp_m + am * 16 + (lid >> 2);
            int n = n0 + warp_n + an * 8 + (lid & 3) * 2;
            float b0 = bias[n], b1 = bias[n + 1];
            int h = n >> 6, d = n & 63;
            #pragma unroll
            for (int rr = 0; rr < 2; rr++) {
                int mm = m + rr * 8;
                int bb = mm >> 11;
                int t  = mm & (TT - 1);
                float v0 = acc[am][an][rr*2+0] + b0;
                float v1 = acc[am][an][rr*2+1] + b1;
                if (which == 2) {
                    float2 r2 = make_float2(v0, v1);
                    *(float2*)&g_v[((size_t)(bb * HH + h) * TT + t) * DH + d] = r2;
                } else {
                    float* __restrict__ out = (which == 0) ? g_q : g_k;
                    out[((size_t)(bb * HH + h) * DH + d) * TT + t]     = v0;
                    out[((size_t)(bb * HH + h) * DH + d + 1) * TT + t] = v1;
                }
            }
        }
    }
}

// ---------------------------------------------------------------------------
// Kernel 2: causal flash attention, fp32, register-tiled (unchanged from R2)
// ---------------------------------------------------------------------------
#define BQ 64
#define BK 64
#define APAD 68
#define ATTN_SMEM_BYTES (4 * 64 * APAD * 4)

__global__ __launch_bounds__(256) void attn_kernel()
{
    extern __shared__ float sm[];
    float* Qs = sm;
    float* Ks = sm + 64 * APAD;
    float* Vs = sm + 2 * 64 * APAD;
    float* Ps = sm + 3 * 64 * APAD;

    const int tid = threadIdx.x;
    const int tx = tid & 15;
    const int ty = tid >> 4;
    const int bh = blockIdx.y;
    const int qt = gridDim.x - 1 - blockIdx.x;
    const int q0 = qt * BQ;

    const float* __restrict__ Qg = g_q + (size_t)bh * DH * TT;
    const float* __restrict__ Kg = g_k + (size_t)bh * DH * TT;
    const float* __restrict__ Vg = g_v + (size_t)bh * TT * DH;

    #pragma unroll
    for (int it = 0; it < 4; it++) {
        int idx = tid + it * 256;
        int d  = idx >> 4;
        int c4 = (idx & 15) * 4;
        float4 v = *(const float4*)&Qg[(size_t)d * TT + q0 + c4];
        float* dst = &Qs[d * APAD + c4];
        dst[0] = v.x * 0.125f; dst[1] = v.y * 0.125f;
        dst[2] = v.z * 0.125f; dst[3] = v.w * 0.125f;
    }

    float o[4][4] = {};
    float mrow[4] = {-1e30f, -1e30f, -1e30f, -1e30f};
    float lrow[4] = {};

    for (int j0 = 0; j0 <= q0; j0 += BK) {
        __syncthreads();
        #pragma unroll
        for (int it = 0; it < 4; it++) {
            int idx = tid + it * 256;
            int r  = idx >> 4;
            int c4 = (idx & 15) * 4;
            float4 kv = *(const float4*)&Kg[(size_t)r * TT + j0 + c4];
            *(float4*)&Ks[r * APAD + c4] = kv;
            float4 vv = *(const float4*)&Vg[(size_t)(j0 + r) * DH + c4];
            *(float4*)&Vs[r * APAD + c4] = vv;
        }
        __syncthreads();

        float s[4][4] = {};
        #pragma unroll
        for (int k = 0; k < 64; k++) {
            float4 a = *(const float4*)&Qs[k * APAD + ty * 4];
            float4 b = *(const float4*)&Ks[k * APAD + tx * 4];
            float am[4] = {a.x, a.y, a.z, a.w};
            float bn[4] = {b.x, b.y, b.z, b.w};
            #pragma unroll
            for (int i = 0; i < 4; i++)
                #pragma unroll
                for (int j = 0; j < 4; j++)
                    s[i][j] = fmaf(am[i], bn[j], s[i][j]);
        }

        if (j0 == q0) {
            #pragma unroll
            for (int i = 0; i < 4; i++)
                #pragma unroll
                for (int j = 0; j < 4; j++)
                    if (tx * 4 + j > ty * 4 + i) s[i][j] = -1e30f;
        }

        #pragma unroll
        for (int i = 0; i < 4; i++) {
            float tm = fmaxf(fmaxf(s[i][0], s[i][1]), fmaxf(s[i][2], s[i][3]));
            tm = fmaxf(tm, __shfl_xor_sync(0xffffffffu, tm, 1));
            tm = fmaxf(tm, __shfl_xor_sync(0xffffffffu, tm, 2));
            tm = fmaxf(tm, __shfl_xor_sync(0xffffffffu, tm, 4));
            tm = fmaxf(tm, __shfl_xor_sync(0xffffffffu, tm, 8));
            float mnew = fmaxf(mrow[i], tm);
            float corr = __expf(mrow[i] - mnew);
            mrow[i] = mnew;
            float p0 = __expf(s[i][0] - mnew);
            float p1 = __expf(s[i][1] - mnew);
            float p2 = __expf(s[i][2] - mnew);
            float p3 = __expf(s[i][3] - mnew);
            s[i][0] = p0; s[i][1] = p1; s[i][2] = p2; s[i][3] = p3;
            lrow[i] = lrow[i] * corr + ((p0 + p1) + (p2 + p3));
            o[i][0] *= corr; o[i][1] *= corr; o[i][2] *= corr; o[i][3] *= corr;
        }

        #pragma unroll
        for (int j = 0; j < 4; j++) {
            float4 pv = make_float4(s[0][j], s[1][j], s[2][j], s[3][j]);
            *(float4*)&Ps[(tx * 4 + j) * APAD + ty * 4] = pv;
        }
        __syncthreads();

        #pragma unroll
        for (int k = 0; k < 64; k++) {
            float4 a = *(const float4*)&Ps[k * APAD + ty * 4];
            float4 b = *(const float4*)&Vs[k * APAD + tx * 4];
            float am[4] = {a.x, a.y, a.z, a.w};
            float bn[4] = {b.x, b.y, b.z, b.w};
            #pragma unroll
            for (int i = 0; i < 4; i++)
                #pragma unroll
                for (int j = 0; j < 4; j++)
                    o[i][j] = fmaf(am[i], bn[j], o[i][j]);
        }
    }

    const int bb = bh >> 4;
    const int h  = bh & 15;
    #pragma unroll
    for (int i = 0; i < 4; i++) {
        float l = lrow[i];
        l += __shfl_xor_sync(0xffffffffu, l, 1);
        l += __shfl_xor_sync(0xffffffffu, l, 2);
        l += __shfl_xor_sync(0xffffffffu, l, 4);
        l += __shfl_xor_sync(0xffffffffu, l, 8);
        float inv = 1.f / l;
        int t = q0 + ty * 4 + i;
        float4 r;
        r.x = o[i][0] * inv; r.y = o[i][1] * inv;
        r.z = o[i][2] * inv; r.w = o[i][3] * inv;
        *(float4*)&g_att[((size_t)(bb * TT + t)) * DD + h * DH + tx * 4] = r;
    }
}

// ---------------------------------------------------------------------------
// Kernel 3: residual add + LayerNorm
// ---------------------------------------------------------------------------
__global__ __launch_bounds__(256) void ln_kernel(
    const float* __restrict__ x,
    const float* __restrict__ gamma,
    const float* __restrict__ beta,
    float* __restrict__ out)
{
    __shared__ float ybuf[DD];
    __shared__ float red1[8], red2[8];
    __shared__ float s_mean, s_rstd;

    const int row = blockIdx.x;
    const int tid = threadIdx.x;
    const size_t base = (size_t)row * DD;

    float4 av = ((const float4*)(g_att + base))[tid];
    float4 xv = ((const float4*)(x + base))[tid];
    float4 y;
    y.x = av.x + xv.x; y.y = av.y + xv.y;
    y.z = av.z + xv.z; y.w = av.w + xv.w;
    ((float4*)ybuf)[tid] = y;

    float s1 = y.x + y.y + y.z + y.w;
    float s2 = y.x*y.x + y.y*y.y + y.z*y.z + y.w*y.w;
    #pragma unroll
    for (int off = 16; off > 0; off >>= 1) {
        s1 += __shfl_xor_sync(0xffffffffu, s1, off);
        s2 += __shfl_xor_sync(0xffffffffu, s2, off);
    }
    if ((tid & 31) == 0) { red1[tid >> 5] = s1; red2[tid >> 5] = s2; }
    __syncthreads();
    if (tid < 32) {
        float r1 = (tid < 8) ? red1[tid] : 0.f;
        float r2 = (tid < 8) ? red2[tid] : 0.f;
        #pragma unroll
        for (int off = 4; off > 0; off >>= 1) {
            r1 += __shfl_xor_sync(0xffffffffu, r1, off);
            r2 += __shfl_xor_sync(0xffffffffu, r2, off);
        }
        if (tid == 0) {
            float mean = r1 * (1.f / DD);
            float var  = r2 * (1.f / DD) - mean * mean;
            s_mean = mean;
            s_rstd = rsqrtf(var + 1e-5f);
        }
    }
    __syncthreads();

    const float mean = s_mean, rstd = s_rstd;
    float4 yl = ((const float4*)ybuf)[tid];
    float4 g4 = ((const float4*)gamma)[tid];
    float4 b4 = ((const float4*)beta)[tid];
    float4 r;
    r.x = (yl.x - mean) * rstd * g4.x + b4.x;
    r.y = (yl.y - mean) * rstd * g4.y + b4.y;
    r.z = (yl.z - mean) * rstd * g4.z + b4.z;
    r.w = (yl.w - mean) * rstd * g4.w + b4.w;
    ((float4*)(out + base))[tid] = r;
}

// ---------------------------------------------------------------------------
extern "C" void kernel_launch(void* const* d_in, const int* in_sizes, int n_in,
                              void* d_out, int out_size)
{
    const float* x     = (const float*)d_in[0];
    const float* Wq    = (const float*)d_in[1];
    const float* bq    = (const float*)d_in[2];
    const float* Wk    = (const float*)d_in[3];
    const float* bk    = (const float*)d_in[4];
    const float* Wv    = (const float*)d_in[5];
    const float* bv    = (const float*)d_in[6];
    const float* gamma = (const float*)d_in[7];
    const float* beta  = (const float*)d_in[8];
    float* out = (float*)d_out;

    static bool attr_done = false;
    if (!attr_done) {
        cudaFuncSetAttribute(attn_kernel,
                             cudaFuncAttributeMaxDynamicSharedMemorySize,
                             ATTN_SMEM_BYTES);
        cudaFuncSetAttribute(qkv_mma_kernel,
                             cudaFuncAttributeMaxDynamicSharedMemorySize,
                             GEMM_SMEM);
        attr_done = true;
    }

    __nv_bfloat16 *xh, *xl, *wh, *wl;
    cudaGetSymbolAddress((void**)&xh, g_x_hi);
    cudaGetSymbolAddress((void**)&xl, g_x_lo);
    cudaGetSymbolAddress((void**)&wh, g_w_hi);
    cudaGetSymbolAddress((void**)&wl, g_w_lo);

    const int xn4 = MROWS * DD / 4;
    const int wn4 = DD * DD / 4;
    split_kernel<<<(xn4 + 255) / 256, 256>>>(x,  xh, xl, xn4);
    split_kernel<<<(wn4 + 255) / 256, 256>>>(Wq, wh + 0 * (size_t)DD * DD, wl + 0 * (size_t)DD * DD, wn4);
    split_kernel<<<(wn4 + 255) / 256, 256>>>(Wk, wh + 1 * (size_t)DD * DD, wl + 1 * (size_t)DD * DD, wn4);
    split_kernel<<<(wn4 + 255) / 256, 256>>>(Wv, wh + 2 * (size_t)DD * DD, wl + 2 * (size_t)DD * DD, wn4);

    dim3 g1(DD / 128, MROWS / 128, 3);
    qkv_mma_kernel<<<g1, 256, GEMM_SMEM>>>(bq, bk, bv);

    dim3 g2(TT / BQ, BB * HH);
    attn_kernel<<<g2, 256, ATTN_SMEM_BYTES>>>();

    ln_kernel<<<MROWS, 256>>>(x, gamma, beta, out);
}

// round 5
// speedup vs baseline: 3.1586x; 1.4531x over previous
#include <cuda_runtime.h>
#include <cuda_bf16.h>
#include <cstdint>

#define BB 4
#define TT 2048
#define DD 1024
#define HH 16
#define DH 64
#define MROWS (BB*TT)          // 8192
#define BH (BB*HH)             // 64

// attention output
__device__ float g_att[(size_t)BB*TT*DD];

// bf16 split GEMM inputs
__device__ __nv_bfloat16 g_x_hi[(size_t)MROWS*DD];
__device__ __nv_bfloat16 g_x_lo[(size_t)MROWS*DD];
__device__ __nv_bfloat16 g_w_hi[3][(size_t)DD*DD];
__device__ __nv_bfloat16 g_w_lo[3][(size_t)DD*DD];

// bf16 split Q/K/V, [bh][t][dh], Q pre-scaled by 0.125
__device__ __nv_bfloat16 g_qh[(size_t)BH*TT*DH];
__device__ __nv_bfloat16 g_ql[(size_t)BH*TT*DH];
__device__ __nv_bfloat16 g_kh[(size_t)BH*TT*DH];
__device__ __nv_bfloat16 g_kl[(size_t)BH*TT*DH];
__device__ __nv_bfloat16 g_vh[(size_t)BH*TT*DH];
__device__ __nv_bfloat16 g_vl[(size_t)BH*TT*DH];

// ---------------------------------------------------------------------------
// helpers (baseline PTX: cp.async + ldmatrix + mma.sync, sm_80+)
// ---------------------------------------------------------------------------
__device__ __forceinline__ uint32_t smem_u32(const void* p) {
    uint32_t a;
    asm("{ .reg .u64 t; cvta.to.shared.u64 t, %1; cvt.u32.u64 %0, t; }" : "=r"(a) : "l"(p));
    return a;
}
#define CP_ASYNC16(dst, src) \
    asm volatile("cp.async.cg.shared.global [%0], [%1], 16;" :: "r"(dst), "l"(src) : "memory")
#define CP_COMMIT() asm volatile("cp.async.commit_group;" ::: "memory")
#define CP_WAIT(n)  asm volatile("cp.async.wait_group %0;" :: "n"(n) : "memory")

#define LDMX4(r, addr) \
    asm volatile("ldmatrix.sync.aligned.m8n8.x4.shared.b16 {%0,%1,%2,%3}, [%4];" \
        : "=r"((r)[0]), "=r"((r)[1]), "=r"((r)[2]), "=r"((r)[3]) : "r"(addr))
#define LDMX4T(r, addr) \
    asm volatile("ldmatrix.sync.aligned.m8n8.x4.trans.shared.b16 {%0,%1,%2,%3}, [%4];" \
        : "=r"((r)[0]), "=r"((r)[1]), "=r"((r)[2]), "=r"((r)[3]) : "r"(addr))

#define MMA_BF16(c, a, b0, b1) \
    asm volatile("mma.sync.aligned.m16n8k16.row.col.f32.bf16.bf16.f32 " \
        "{%0,%1,%2,%3}, {%4,%5,%6,%7}, {%8,%9}, {%0,%1,%2,%3};" \
        : "+f"((c)[0]), "+f"((c)[1]), "+f"((c)[2]), "+f"((c)[3]) \
        : "r"((a)[0]), "r"((a)[1]), "r"((a)[2]), "r"((a)[3]), "r"(b0), "r"(b1))

__device__ __forceinline__ uint32_t pack_bf2(float a, float b) {
    __nv_bfloat162 t(__float2bfloat16_rn(a), __float2bfloat16_rn(b));
    return *(uint32_t*)&t;
}

// ---------------------------------------------------------------------------
// Kernel 0: fp32 -> (bf16 hi, bf16 lo) split
// ---------------------------------------------------------------------------
__global__ __launch_bounds__(256) void split_kernel(
    const float* __restrict__ src,
    __nv_bfloat16* __restrict__ hi,
    __nv_bfloat16* __restrict__ lo, int n4)
{
    int i = blockIdx.x * blockDim.x + threadIdx.x;
    if (i >= n4) return;
    float4 v = ((const float4*)src)[i];
    __nv_bfloat16 h0 = __float2bfloat16_rn(v.x);
    __nv_bfloat16 h1 = __float2bfloat16_rn(v.y);
    __nv_bfloat16 h2 = __float2bfloat16_rn(v.z);
    __nv_bfloat16 h3 = __float2bfloat16_rn(v.w);
    __nv_bfloat16 l0 = __float2bfloat16_rn(v.x - __bfloat162float(h0));
    __nv_bfloat16 l1 = __float2bfloat16_rn(v.y - __bfloat162float(h1));
    __nv_bfloat16 l2 = __float2bfloat16_rn(v.z - __bfloat162float(h2));
    __nv_bfloat16 l3 = __float2bfloat16_rn(v.w - __bfloat162float(h3));
    ((__nv_bfloat162*)hi)[2*i]   = __nv_bfloat162(h0, h1);
    ((__nv_bfloat162*)hi)[2*i+1] = __nv_bfloat162(h2, h3);
    ((__nv_bfloat162*)lo)[2*i]   = __nv_bfloat162(l0, l1);
    ((__nv_bfloat162*)lo)[2*i+1] = __nv_bfloat162(l2, l3);
}

// ---------------------------------------------------------------------------
// Kernel 1: QKV GEMM, mma.sync bf16-split, 128x128x32 tile, cp.async 2-stage.
// Epilogue: +bias, (Q: *0.125), re-split to bf16 hi/lo into [bh][t][dh].
// ---------------------------------------------------------------------------
#define RSTR 80
#define OPB  (128 * RSTR)
#define BUFB (4 * OPB)
#define GEMM_SMEM (2 * BUFB)

__global__ __launch_bounds__(256) void qkv_mma_kernel(
    const float* __restrict__ bq,
    const float* __restrict__ bk,
    const float* __restrict__ bv)
{
    extern __shared__ uint8_t dsm[];
    const uint32_t sbase = smem_u32(dsm);

    const int which = blockIdx.z;
    const __nv_bfloat16* __restrict__ Ah = g_x_hi;
    const __nv_bfloat16* __restrict__ Al = g_x_lo;
    const __nv_bfloat16* __restrict__ Bh = g_w_hi[which];
    const __nv_bfloat16* __restrict__ Bl = g_w_lo[which];
    const float* __restrict__ bias = (which == 0) ? bq : (which == 1) ? bk : bv;

    const int m0 = blockIdx.y * 128;
    const int n0 = blockIdx.x * 128;
    const int tid = threadIdx.x;
    const int wid = tid >> 5;
    const int lid = tid & 31;
    const int warp_m = (wid & 1) * 64;
    const int warp_n = (wid >> 1) * 32;
    const int lrow = lid & 15;
    const int lhalf = lid >> 4;

    float acc[4][4][4] = {};

    auto load_chunk = [&](int c, int buf) {
        const uint32_t sb = sbase + buf * BUFB;
        #pragma unroll
        for (int i = 0; i < 2; i++) {
            int idx = tid + 256 * i;
            int r = idx >> 2, q = idx & 3;
            uint32_t so = r * RSTR + q * 16;
            size_t goA = (size_t)(m0 + r) * DD + c * 32 + q * 8;
            size_t goB = (size_t)(n0 + r) * DD + c * 32 + q * 8;
            CP_ASYNC16(sb + so,           Ah + goA);
            CP_ASYNC16(sb + OPB + so,     Al + goA);
            CP_ASYNC16(sb + 2*OPB + so,   Bh + goB);
            CP_ASYNC16(sb + 3*OPB + so,   Bl + goB);
        }
    };

    load_chunk(0, 0);
    CP_COMMIT();

    int buf = 0;
    #pragma unroll 1
    for (int c = 0; c < 32; c++) {
        if (c + 1 < 32) { load_chunk(c + 1, buf ^ 1); CP_COMMIT(); }
        if (c + 1 < 32) { CP_WAIT(1); } else { CP_WAIT(0); }
        __syncthreads();

        const uint32_t aw = sbase + buf * BUFB;
        #pragma unroll
        for (int ks = 0; ks < 2; ks++) {
            uint32_t ah[4][4], al[4][4], bh2[2][4], bl2[2][4];
            #pragma unroll
            for (int am = 0; am < 4; am++) {
                uint32_t addr = aw + (warp_m + am * 16 + lrow) * RSTR + ks * 32 + lhalf * 16;
                LDMX4(ah[am], addr);
                LDMX4(al[am], addr + OPB);
            }
            #pragma unroll
            for (int g = 0; g < 2; g++) {
                uint32_t addr = aw + 2*OPB + (warp_n + g * 16 + lrow) * RSTR + ks * 32 + lhalf * 16;
                LDMX4(bh2[g], addr);
                LDMX4(bl2[g], addr + OPB);
            }
            #pragma unroll
            for (int am = 0; am < 4; am++)
                #pragma unroll
                for (int an = 0; an < 4; an++) {
                    int g = an >> 1, s = an & 1;
                    MMA_BF16(acc[am][an], ah[am], bh2[g][s], bh2[g][s+2]);
                    MMA_BF16(acc[am][an], ah[am], bl2[g][s], bl2[g][s+2]);
                    MMA_BF16(acc[am][an], al[am], bh2[g][s], bh2[g][s+2]);
                }
        }
        __syncthreads();
        buf ^= 1;
    }

    __nv_bfloat16* __restrict__ Xh = (which == 0) ? g_qh : (which == 1) ? g_kh : g_vh;
    __nv_bfloat16* __restrict__ Xl = (which == 0) ? g_ql : (which == 1) ? g_kl : g_vl;
    const float sc = (which == 0) ? 0.125f : 1.0f;

    #pragma unroll
    for (int am = 0; am < 4; am++) {
        #pragma unroll
        for (int an = 0; an < 4; an++) {
            int m = m0 + warp_m + am * 16 + (lid >> 2);
            int n = n0 + warp_n + an * 8 + (lid & 3) * 2;
            float b0 = bias[n], b1 = bias[n + 1];
            int h = n >> 6, d = n & 63;
            #pragma unroll
            for (int rr = 0; rr < 2; rr++) {
                int mm = m + rr * 8;
                int bb = mm >> 11;
                int t  = mm & (TT - 1);
                float v0 = (acc[am][an][rr*2+0] + b0) * sc;
                float v1 = (acc[am][an][rr*2+1] + b1) * sc;
                __nv_bfloat16 h0 = __float2bfloat16_rn(v0);
                __nv_bfloat16 h1 = __float2bfloat16_rn(v1);
                __nv_bfloat16 e0 = __float2bfloat16_rn(v0 - __bfloat162float(h0));
                __nv_bfloat16 e1 = __float2bfloat16_rn(v1 - __bfloat162float(h1));
                size_t o = ((size_t)(bb * HH + h) * TT + t) * DH + d;
                *(__nv_bfloat162*)&Xh[o] = __nv_bfloat162(h0, h1);
                *(__nv_bfloat162*)&Xl[o] = __nv_bfloat162(e0, e1);
            }
        }
    }
}

// ---------------------------------------------------------------------------
// Kernel 2: causal flash attention with mma.sync, bf16-split.
// CTA: 128 threads (4 warps x 16 q-rows = 64 q-rows), K tiles of 64.
// ---------------------------------------------------------------------------
#define ABQ 64
#define ABK 64
#define ASTR 144                       // 64 bf16 = 128B data + 16B pad
#define AT_QH 0
#define AT_QL (64*ASTR)
#define AT_KH (2*64*ASTR)
#define AT_KL (3*64*ASTR)
#define AT_VH (4*64*ASTR)
#define AT_VL (5*64*ASTR)
#define ATTN_SMEM (6*64*ASTR)          // 55296

__global__ __launch_bounds__(128) void attn_kernel()
{
    extern __shared__ uint8_t asm8[];
    const uint32_t sb = smem_u32(asm8);

    const int tid = threadIdx.x;
    const int wid = tid >> 5;
    const int lid = tid & 31;
    const int lrow = lid & 15;
    const int lhalf = lid >> 4;
    const int bh = blockIdx.y;
    const int qt = gridDim.x - 1 - blockIdx.x;       // heavy first
    const int q0 = qt * ABQ;
    const int qw = q0 + wid * 16;                    // warp q base

    const size_t hb = (size_t)bh * TT * DH;

    // load Q tile (hi/lo): 64 rows x 128B
    #pragma unroll
    for (int it = 0; it < 4; it++) {
        int idx = tid + it * 128;
        int r = idx >> 3, qd = idx & 7;
        uint32_t so = (uint32_t)(r * ASTR + qd * 16);
        size_t go = hb + (size_t)(q0 + r) * DH + qd * 8;
        *(uint4*)(asm8 + AT_QH + so) = *(const uint4*)(g_qh + go);
        *(uint4*)(asm8 + AT_QL + so) = *(const uint4*)(g_ql + go);
    }
    __syncthreads();

    // Q fragments (persistent): 4 k-chunks, hi/lo
    uint32_t qfh[4][4], qfl[4][4];
    #pragma unroll
    for (int kc = 0; kc < 4; kc++) {
        uint32_t addr = sb + AT_QH + (wid * 16 + lrow) * ASTR + kc * 32 + lhalf * 16;
        LDMX4(qfh[kc], addr);
        LDMX4(qfl[kc], addr + (AT_QL - AT_QH));
    }

    float o[8][4] = {};
    float mrow[2] = {-1e30f, -1e30f};
    float lrow2[2] = {0.f, 0.f};

    #pragma unroll 1
    for (int j0 = 0; j0 <= q0; j0 += ABK) {
        __syncthreads();
        // load K/V tiles (hi/lo)
        #pragma unroll
        for (int it = 0; it < 4; it++) {
            int idx = tid + it * 128;
            int r = idx >> 3, qd = idx & 7;
            uint32_t so = (uint32_t)(r * ASTR + qd * 16);
            size_t go = hb + (size_t)(j0 + r) * DH + qd * 8;
            *(uint4*)(asm8 + AT_KH + so) = *(const uint4*)(g_kh + go);
            *(uint4*)(asm8 + AT_KL + so) = *(const uint4*)(g_kl + go);
            *(uint4*)(asm8 + AT_VH + so) = *(const uint4*)(g_vh + go);
            *(uint4*)(asm8 + AT_VL + so) = *(const uint4*)(g_vl + go);
        }
        __syncthreads();

        if (j0 > qw + 15) continue;       // fully masked for this warp

        // ---- S = Q K^T (3-term split) ----
        float s[8][4] = {};
        #pragma unroll
        for (int ng = 0; ng < 4; ng++) {
            #pragma unroll
            for (int kc = 0; kc < 4; kc++) {
                uint32_t kh[4], kl[4];
                uint32_t addr = sb + AT_KH + (ng * 16 + lrow) * ASTR + kc * 32 + lhalf * 16;
                LDMX4(kh, addr);
                LDMX4(kl, addr + (AT_KL - AT_KH));
                #pragma unroll
                for (int s2 = 0; s2 < 2; s2++) {
                    MMA_BF16(s[2*ng+s2], qfh[kc], kh[s2], kh[s2+2]);
                    MMA_BF16(s[2*ng+s2], qfh[kc], kl[s2], kl[s2+2]);
                    MMA_BF16(s[2*ng+s2], qfl[kc], kh[s2], kh[s2+2]);
                }
            }
        }

        // causal mask (diagonal band tiles only)
        if (j0 + ABK - 1 > qw) {
            int r0 = qw + (lid >> 2), r1 = r0 + 8;
            #pragma unroll
            for (int nf = 0; nf < 8; nf++) {
                int c = j0 + nf * 8 + (lid & 3) * 2;
                if (c > r0)     s[nf][0] = -1e30f;
                if (c + 1 > r0) s[nf][1] = -1e30f;
                if (c > r1)     s[nf][2] = -1e30f;
                if (c + 1 > r1) s[nf][3] = -1e30f;
            }
        }

        // ---- online softmax ----
        float tm0 = -1e30f, tm1 = -1e30f;
        #pragma unroll
        for (int nf = 0; nf < 8; nf++) {
            tm0 = fmaxf(tm0, fmaxf(s[nf][0], s[nf][1]));
            tm1 = fmaxf(tm1, fmaxf(s[nf][2], s[nf][3]));
        }
        tm0 = fmaxf(tm0, __shfl_xor_sync(0xffffffffu, tm0, 1));
        tm0 = fmaxf(tm0, __shfl_xor_sync(0xffffffffu, tm0, 2));
        tm1 = fmaxf(tm1, __shfl_xor_sync(0xffffffffu, tm1, 1));
        tm1 = fmaxf(tm1, __shfl_xor_sync(0xffffffffu, tm1, 2));
        float mn0 = fmaxf(mrow[0], tm0);
        float mn1 = fmaxf(mrow[1], tm1);
        float cr0 = __expf(mrow[0] - mn0);
        float cr1 = __expf(mrow[1] - mn1);
        mrow[0] = mn0; mrow[1] = mn1;
        float ls0 = 0.f, ls1 = 0.f;
        #pragma unroll
        for (int nf = 0; nf < 8; nf++) {
            s[nf][0] = __expf(s[nf][0] - mn0);
            s[nf][1] = __expf(s[nf][1] - mn0);
            s[nf][2] = __expf(s[nf][2] - mn1);
            s[nf][3] = __expf(s[nf][3] - mn1);
            ls0 += s[nf][0] + s[nf][1];
            ls1 += s[nf][2] + s[nf][3];
            o[nf][0] *= cr0; o[nf][1] *= cr0;
            o[nf][2] *= cr1; o[nf][3] *= cr1;
        }
        lrow2[0] = lrow2[0] * cr0 + ls0;
        lrow2[1] = lrow2[1] * cr1 + ls1;

        // ---- pack P to bf16 hi/lo A-fragments ----
        uint32_t pah[4][4], pal[4][4];
        #pragma unroll
        for (int kc = 0; kc < 4; kc++) {
            #pragma unroll
            for (int half = 0; half < 2; half++) {        // nfrag 2kc+half
                int nf = 2 * kc + half;
                float v0 = s[nf][0], v1 = s[nf][1], v2 = s[nf][2], v3 = s[nf][3];
                __nv_bfloat16 h0 = __float2bfloat16_rn(v0);
                __nv_bfloat16 h1 = __float2bfloat16_rn(v1);
                __nv_bfloat16 h2 = __float2bfloat16_rn(v2);
                __nv_bfloat16 h3 = __float2bfloat16_rn(v3);
                __nv_bfloat162 ph01(h0, h1), ph23(h2, h3);
                pah[kc][half*2+0] = *(uint32_t*)&ph01;
                pah[kc][half*2+1] = *(uint32_t*)&ph23;
                pal[kc][half*2+0] = pack_bf2(v0 - __bfloat162float(h0), v1 - __bfloat162float(h1));
                pal[kc][half*2+1] = pack_bf2(v2 - __bfloat162float(h2), v3 - __bfloat162float(h3));
            }
        }
        // reorder: A frag regs must be {c0c1(nf even), c2c3(nf even), c0c1(nf odd), c2c3(nf odd)}
        // layout above: [kc][0]=even c0c1, [1]=even c2c3, [2]=odd c0c1, [3]=odd c2c3  — already correct.

        // ---- O += P V (3-term split) ----
        #pragma unroll
        for (int dg = 0; dg < 4; dg++) {
            #pragma unroll
            for (int tc = 0; tc < 4; tc++) {
                uint32_t vh[4], vl[4];
                int lt = (lid & 7) + ((lid >> 4) << 3);
                int ld = ((lid >> 3) & 1) << 3;
                uint32_t addr = sb + AT_VH + (tc * 16 + lt) * ASTR + (dg * 16 + ld) * 2;
                LDMX4T(vh, addr);
                LDMX4T(vl, addr + (AT_VL - AT_VH));
                #pragma unroll
                for (int s2 = 0; s2 < 2; s2++) {
                    MMA_BF16(o[2*dg+s2], pah[tc], vh[s2], vh[s2+2]);
                    MMA_BF16(o[2*dg+s2], pah[tc], vl[s2], vl[s2+2]);
                    MMA_BF16(o[2*dg+s2], pal[tc], vh[s2], vh[s2+2]);
                }
            }
        }
    }

    // final: reduce l over the quad, normalize, write out
    float l0 = lrow2[0], l1 = lrow2[1];
    l0 += __shfl_xor_sync(0xffffffffu, l0, 1);
    l0 += __shfl_xor_sync(0xffffffffu, l0, 2);
    l1 += __shfl_xor_sync(0xffffffffu, l1, 1);
    l1 += __shfl_xor_sync(0xffffffffu, l1, 2);
    float inv0 = 1.f / l0, inv1 = 1.f / l1;

    const int bb = bh >> 4;
    const int h  = bh & 15;
    int t0 = qw + (lid >> 2);
    int t1 = t0 + 8;
    #pragma unroll
    for (int nf = 0; nf < 8; nf++) {
        int dc = h * DH + nf * 8 + (lid & 3) * 2;
        float2 r0 = make_float2(o[nf][0] * inv0, o[nf][1] * inv0);
        float2 r1 = make_float2(o[nf][2] * inv1, o[nf][3] * inv1);
        *(float2*)&g_att[((size_t)(bb * TT + t0)) * DD + dc] = r0;
        *(float2*)&g_att[((size_t)(bb * TT + t1)) * DD + dc] = r1;
    }
}

// ---------------------------------------------------------------------------
// Kernel 3: residual add + LayerNorm
// ---------------------------------------------------------------------------
__global__ __launch_bounds__(256) void ln_kernel(
    const float* __restrict__ x,
    const float* __restrict__ gamma,
    const float* __restrict__ beta,
    float* __restrict__ out)
{
    __shared__ float ybuf[DD];
    __shared__ float red1[8], red2[8];
    __shared__ float s_mean, s_rstd;

    const int row = blockIdx.x;
    const int tid = threadIdx.x;
    const size_t base = (size_t)row * DD;

    float4 av = ((const float4*)(g_att + base))[tid];
    float4 xv = ((const float4*)(x + base))[tid];
    float4 y;
    y.x = av.x + xv.x; y.y = av.y + xv.y;
    y.z = av.z + xv.z; y.w = av.w + xv.w;
    ((float4*)ybuf)[tid] = y;

    float s1 = y.x + y.y + y.z + y.w;
    float s2 = y.x*y.x + y.y*y.y + y.z*y.z + y.w*y.w;
    #pragma unroll
    for (int off = 16; off > 0; off >>= 1) {
        s1 += __shfl_xor_sync(0xffffffffu, s1, off);
        s2 += __shfl_xor_sync(0xffffffffu, s2, off);
    }
    if ((tid & 31) == 0) { red1[tid >> 5] = s1; red2[tid >> 5] = s2; }
    __syncthreads();
    if (tid < 32) {
        float r1 = (tid < 8) ? red1[tid] : 0.f;
        float r2 = (tid < 8) ? red2[tid] : 0.f;
        #pragma unroll
        for (int off = 4; off > 0; off >>= 1) {
            r1 += __shfl_xor_sync(0xffffffffu, r1, off);
            r2 += __shfl_xor_sync(0xffffffffu, r2, off);
        }
        if (tid == 0) {
            float mean = r1 * (1.f / DD);
            float var  = r2 * (1.f / DD) - mean * mean;
            s_mean = mean;
            s_rstd = rsqrtf(var + 1e-5f);
        }
    }
    __syncthreads();

    const float mean = s_mean, rstd = s_rstd;
    float4 yl = ((const float4*)ybuf)[tid];
    float4 g4 = ((const float4*)gamma)[tid];
    float4 b4 = ((const float4*)beta)[tid];
    float4 r;
    r.x = (yl.x - mean) * rstd * g4.x + b4.x;
    r.y = (yl.y - mean) * rstd * g4.y + b4.y;
    r.z = (yl.z - mean) * rstd * g4.z + b4.z;
    r.w = (yl.w - mean) * rstd * g4.w + b4.w;
    ((float4*)(out + base))[tid] = r;
}

// ---------------------------------------------------------------------------
extern "C" void kernel_launch(void* const* d_in, const int* in_sizes, int n_in,
                              void* d_out, int out_size)
{
    const float* x     = (const float*)d_in[0];
    const float* Wq    = (const float*)d_in[1];
    const float* bq    = (const float*)d_in[2];
    const float* Wk    = (const float*)d_in[3];
    const float* bk    = (const float*)d_in[4];
    const float* Wv    = (const float*)d_in[5];
    const float* bv    = (const float*)d_in[6];
    const float* gamma = (const float*)d_in[7];
    const float* beta  = (const float*)d_in[8];
    float* out = (float*)d_out;

    static bool attr_done = false;
    if (!attr_done) {
        cudaFuncSetAttribute(attn_kernel,
                             cudaFuncAttributeMaxDynamicSharedMemorySize,
                             ATTN_SMEM);
        cudaFuncSetAttribute(qkv_mma_kernel,
                             cudaFuncAttributeMaxDynamicSharedMemorySize,
                             GEMM_SMEM);
        attr_done = true;
    }

    __nv_bfloat16 *xh, *xl, *wh, *wl;
    cudaGetSymbolAddress((void**)&xh, g_x_hi);
    cudaGetSymbolAddress((void**)&xl, g_x_lo);
    cudaGetSymbolAddress((void**)&wh, g_w_hi);
    cudaGetSymbolAddress((void**)&wl, g_w_lo);

    const int xn4 = MROWS * DD / 4;
    const int wn4 = DD * DD / 4;
    split_kernel<<<(xn4 + 255) / 256, 256>>>(x,  xh, xl, xn4);
    split_kernel<<<(wn4 + 255) / 256, 256>>>(Wq, wh + 0 * (size_t)DD * DD, wl + 0 * (size_t)DD * DD, wn4);
    split_kernel<<<(wn4 + 255) / 256, 256>>>(Wk, wh + 1 * (size_t)DD * DD, wl + 1 * (size_t)DD * DD, wn4);
    split_kernel<<<(wn4 + 255) / 256, 256>>>(Wv, wh + 2 * (size_t)DD * DD, wl + 2 * (size_t)DD * DD, wn4);

    dim3 g1(DD / 128, MROWS / 128, 3);
    qkv_mma_kernel<<<g1, 256, GEMM_SMEM>>>(bq, bk, bv);

    dim3 g2(TT / ABQ, BH);
    attn_kernel<<<g2, 128, ATTN_SMEM>>>();

    ln_kernel<<<MROWS, 256>>>(x, gamma, beta, out);
}